// round 5
// baseline (speedup 1.0000x reference)
#include <cuda_runtime.h>

#define NB   8
#define CIN  64
#define HH   128
#define WW   128
#define LL   (HH*WW)      /* 16384 */
#define KK   576
#define COUT 128
#define TOFF 4096         /* keys ~N(0,42); 4096 = 98 sigma */
#define TSIZE 8200
#define SENT 0x7FFFFFFF

#define BM   32           /* reps per conv block */
#define CONV_SMEM (BM*KK*4)   /* 73728 B dynamic */

// ---------------- scratch (static device globals) ----------------
__device__ int   d_table[NB*TSIZE];
__device__ int   d_summ [NB*LL];
__device__ int   d_ridx [NB*LL];
__device__ int   d_list [NB*LL];
__device__ int   d_count;
__device__ float d_wt4  [KK*COUT];
__device__ float d_tmp2 [(size_t)NB*LL*COUT];

// ---------------- 1. setup: table init + weight relayout (fused) ----------
__global__ void setup_k(const float* __restrict__ weight) {
    int i = blockIdx.x*blockDim.x + threadIdx.x;
    if (i < NB*TSIZE) d_table[i] = SENT;
    if (i == 0) d_count = 0;
    if (i < KK*COUT) {
        int k = i >> 7;
        int o = i & 127;
        d_wt4[(k >> 2)*(COUT*4) + o*4 + (k & 3)] = weight[o*KK + k];
    }
}

// ---------------- 2. summ: EXACT sequential-order 576-sum -> int key -------
// R3 version verbatim (fastest measured). Per output: p = c*9+ki*3+kj ascending,
// ONE accumulator. Bit-exact vs reference. DO NOT reassociate or restructure.
__global__ void summ_k(const float* __restrict__ fmap) {
    int t = blockIdx.x*blockDim.x + threadIdx.x;
    if (t >= NB*HH*(WW/2)) return;
    int w0 = (t & 63) << 1;
    int h  = (t >> 6) & 127;
    int n  = t >> 13;

    float a0 = 0.f, a1 = 0.f;
    const float* base = fmap + (size_t)n*CIN*LL;

    #pragma unroll 4
    for (int c = 0; c < CIN; c++) {
        const float* cp = base + c*LL;
        #pragma unroll
        for (int di = 0; di < 3; di++) {
            int hr = h + di - 1;
            float lft = 0.f, rgt = 0.f, m0 = 0.f, m1 = 0.f;
            if (hr >= 0 && hr < HH) {
                const float* row = cp + hr*WW;
                float2 m = *reinterpret_cast<const float2*>(row + w0);
                m0 = m.x; m1 = m.y;
                lft = (w0 > 0)   ? row[w0-1] : 0.f;
                rgt = (w0 < 126) ? row[w0+2] : 0.f;
            }
            a0 += lft; a0 += m0; a0 += m1;
            a1 += m0;  a1 += m1; a1 += rgt;
        }
    }

    int l0 = h*WW + w0;
    int* sp = d_summ + n*LL + l0;
    int* tb = d_table + n*TSIZE;
    float vals[2] = {a0, a1};
    #pragma unroll
    for (int j = 0; j < 2; j++) {
        float mean = vals[j] / 576.0f;
        float s    = mean * 1000.0f;
        int iv = (int)s;
        iv = max(-TOFF, min(TOFF-1, iv));
        sp[j] = iv;
        atomicMin(&tb[iv + TOFF], l0 + j);
    }
}

// ---------------- 3. compact reps, assign dense rep ids ----------------
__global__ void rep_k() {
    int t = blockIdx.x*blockDim.x + threadIdx.x;
    if (t >= NB*LL) return;
    int n = t >> 14;
    int l = t & (LL-1);
    int v = d_summ[t];
    if (d_table[n*TSIZE + v + TOFF] == l) {
        int idx = atomicAdd(&d_count, 1);
        d_list[idx] = t;
        d_ridx[t]   = idx;
    }
}

// ---------------- 4. conv at reps: BM=32, weight amortized 4x ------------
// 512 threads = 128 o x 4 rep-groups of 8. Dynamic smem 73.7KB. Single wave.
__global__ void __launch_bounds__(512)
conv3_k(const float* __restrict__ fmap, const float* __restrict__ bias) {
    extern __shared__ float patch[];   /* BM*KK floats */

    int o  = threadIdx.x & 127;
    int rg = threadIdx.x >> 7;         /* 0..3 */
    float bo = bias[o];
    int nrep = d_count;
    int nblk = (nrep + BM - 1) / BM;

    for (int b = blockIdx.x; b < nblk; b += gridDim.x) {
        int r0  = b*BM;
        int cnt = min(BM, nrep - r0);

        for (int i = threadIdx.x; i < cnt*KK; i += blockDim.x) {
            int rr = i / KK;
            int e  = i - rr*KK;
            int t  = d_list[r0 + rr];
            int n  = t >> 14;
            int l  = t & (LL-1);
            int h  = l >> 7;
            int w  = l & 127;
            int c  = e / 9;
            int k9 = e - c*9;
            int di = k9 / 3;
            int dj = k9 - di*3;
            int hr = h + di - 1;
            int wc = w + dj - 1;
            float v = 0.f;
            if (hr >= 0 && hr < HH && wc >= 0 && wc < WW)
                v = fmap[((size_t)(n*CIN + c))*LL + hr*WW + wc];
            patch[rr*KK + e] = v;
        }
        __syncthreads();

        float acc[8];
        #pragma unroll
        for (int rr = 0; rr < 8; rr++) acc[rr] = 0.f;
        const float* pbase = patch + rg*8*KK;

        #pragma unroll 2
        for (int k0 = 0; k0 < KK; k0 += 4) {
            float4 wv = *reinterpret_cast<const float4*>(
                d_wt4 + (k0 >> 2)*(COUT*4) + o*4);      /* coalesced, L2-hot */
            #pragma unroll
            for (int rr = 0; rr < 8; rr++) {
                float4 p = *reinterpret_cast<const float4*>(pbase + rr*KK + k0);
                acc[rr] += wv.x*p.x;
                acc[rr] += wv.y*p.y;
                acc[rr] += wv.z*p.z;
                acc[rr] += wv.w*p.w;
            }
        }

        #pragma unroll
        for (int rr = 0; rr < 8; rr++) {
            int rid = r0 + rg*8 + rr;
            if (rid < nrep)
                d_tmp2[(size_t)rid*COUT + o] = acc[rr] + bo;
        }
        __syncthreads();
    }
}

// ---------------- 5. gather (fused rep lookup + smem transpose) ----------
__global__ void gather_t(float* __restrict__ out) {
    __shared__ float sm[32*129];
    __shared__ int   rids[32];

    int n  = blockIdx.x >> 9;
    int lt = blockIdx.x & 511;
    int l0 = lt << 5;
    int tid = threadIdx.x;

    if (tid < 32) {
        int v = d_summ[(n << 14) + l0 + tid];
        int r = d_table[n*TSIZE + v + TOFF];
        rids[tid] = d_ridx[(n << 14) + r];
    }
    __syncthreads();

    #pragma unroll
    for (int j = 0; j < 4; j++) {
        int idx = tid + j*256;
        int row = idx >> 5;
        int o4  = (idx & 31) << 2;
        float4 v = *reinterpret_cast<const float4*>(
            d_tmp2 + (size_t)rids[row]*COUT + o4);
        sm[row*129 + o4 + 0] = v.x;
        sm[row*129 + o4 + 1] = v.y;
        sm[row*129 + o4 + 2] = v.z;
        sm[row*129 + o4 + 3] = v.w;
    }
    __syncthreads();

    #pragma unroll
    for (int j = 0; j < 4; j++) {
        int idx = tid + j*256;
        int o   = idx >> 3;
        int l4  = (idx & 7) << 2;
        float4 v;
        v.x = sm[(l4 + 0)*129 + o];
        v.y = sm[(l4 + 1)*129 + o];
        v.z = sm[(l4 + 2)*129 + o];
        v.w = sm[(l4 + 3)*129 + o];
        *reinterpret_cast<float4*>(
            out + (((size_t)n*COUT + o) << 14) + l0 + l4) = v;
    }
}

// ---------------- launch ----------------
extern "C" void kernel_launch(void* const* d_in, const int* in_sizes, int n_in,
                              void* d_out, int out_size) {
    const float* fmap   = (const float*)d_in[0];
    const float* weight = (const float*)d_in[1];
    const float* bias   = (const float*)d_in[2];
    float* out = (float*)d_out;

    cudaFuncSetAttribute(conv3_k, cudaFuncAttributeMaxDynamicSharedMemorySize, CONV_SMEM);

    setup_k <<<(KK*COUT + 255)/256, 256>>>(weight);      /* #1 */
    summ_k  <<<(NB*HH*(WW/2) + 255)/256, 256>>>(fmap);   /* #2 */
    rep_k   <<<(NB*LL + 255)/256, 256>>>();              /* #3 */
    conv3_k <<<148, 512, CONV_SMEM>>>(fmap, bias);       /* #4 <- profiled */
    gather_t<<<NB*512, 256>>>(out);                      /* #5 */
}

// round 6
// speedup vs baseline: 1.2206x; 1.2206x over previous
#include <cuda_runtime.h>

#define NB   8
#define CIN  64
#define HH   128
#define WW   128
#define LL   (HH*WW)      /* 16384 */
#define KK   576
#define COUT 128
#define TOFF 4096         /* keys ~N(0,42); 4096 = 98 sigma */
#define TSIZE 8200
#define SENT 0x7FFFFFFF

#define BM     16         /* reps per conv tile */
#define NKC    4          /* split-k chunks */
#define KCH    (KK/NKC)   /* 144 k-values per chunk */
#define MAXREP 8192

// ---------------- scratch (static device globals) ----------------
__device__ int   d_table[NB*TSIZE];
__device__ int   d_summ [NB*LL];
__device__ int   d_ridx [NB*LL];
__device__ int   d_list [NB*LL];
__device__ int   d_count;
__device__ float d_wt4  [KK*COUT];
__device__ float d_tmp2 [(size_t)NB*LL*COUT];

// ---------------- 1a. init table + counter ----------------
__global__ void init_k() {
    int i = blockIdx.x*blockDim.x + threadIdx.x;
    if (i < NB*TSIZE) d_table[i] = SENT;
    if (i == 0) d_count = 0;
}

// ---------------- 1b. zero conv accumulator region ----------------
__global__ void zero_k() {
    int i = blockIdx.x*blockDim.x + threadIdx.x;
    float4 z = {0.f, 0.f, 0.f, 0.f};
    if (i < MAXREP*COUT/4)
        reinterpret_cast<float4*>(d_tmp2)[i] = z;
}

// ---------------- 1c. weight relayout: [k/4][o][4] ----------------
__global__ void wt_k(const float* __restrict__ weight) {
    int i = blockIdx.x*blockDim.x + threadIdx.x;
    if (i >= KK*COUT) return;
    int k = i >> 7;
    int o = i & 127;
    d_wt4[(k >> 2)*(COUT*4) + o*4 + (k & 3)] = weight[o*KK + k];
}

// ---------------- 2. summ: EXACT sequential-order 576-sum -> int key -------
// R3 version verbatim (fastest measured). p = c*9+ki*3+kj ascending, ONE
// accumulator per output. Bit-exact vs reference. DO NOT reassociate.
// (Launch #4 -> profiled this round.)
__global__ void summ_k(const float* __restrict__ fmap) {
    int t = blockIdx.x*blockDim.x + threadIdx.x;
    if (t >= NB*HH*(WW/2)) return;
    int w0 = (t & 63) << 1;
    int h  = (t >> 6) & 127;
    int n  = t >> 13;

    float a0 = 0.f, a1 = 0.f;
    const float* base = fmap + (size_t)n*CIN*LL;

    #pragma unroll 4
    for (int c = 0; c < CIN; c++) {
        const float* cp = base + c*LL;
        #pragma unroll
        for (int di = 0; di < 3; di++) {
            int hr = h + di - 1;
            float lft = 0.f, rgt = 0.f, m0 = 0.f, m1 = 0.f;
            if (hr >= 0 && hr < HH) {
                const float* row = cp + hr*WW;
                float2 m = *reinterpret_cast<const float2*>(row + w0);
                m0 = m.x; m1 = m.y;
                lft = (w0 > 0)   ? row[w0-1] : 0.f;
                rgt = (w0 < 126) ? row[w0+2] : 0.f;
            }
            a0 += lft; a0 += m0; a0 += m1;
            a1 += m0;  a1 += m1; a1 += rgt;
        }
    }

    int l0 = h*WW + w0;
    int* sp = d_summ + n*LL + l0;
    int* tb = d_table + n*TSIZE;
    float vals[2] = {a0, a1};
    #pragma unroll
    for (int j = 0; j < 2; j++) {
        float mean = vals[j] / 576.0f;
        float s    = mean * 1000.0f;
        int iv = (int)s;
        iv = max(-TOFF, min(TOFF-1, iv));
        sp[j] = iv;
        atomicMin(&tb[iv + TOFF], l0 + j);
    }
}

// ---------------- 3. compact reps, assign dense rep ids ----------------
__global__ void rep_k() {
    int t = blockIdx.x*blockDim.x + threadIdx.x;
    if (t >= NB*LL) return;
    int n = t >> 14;
    int l = t & (LL-1);
    int v = d_summ[t];
    if (d_table[n*TSIZE + v + TOFF] == l) {
        int idx = atomicAdd(&d_count, 1);
        d_list[idx] = t;
        d_ridx[t]   = idx;
    }
}

// ---------------- 4. conv: split-k x4, BM=16, atomicAdd accumulate -------
// 256 threads = 128 o x 2 rep-groups of 8. 9.2KB smem -> high residency.
// Tile = (kc, rep-block). Weight LDGs batched 4-wide for MLP.
__global__ void __launch_bounds__(256)
conv4_k(const float* __restrict__ fmap) {
    __shared__ float patch[BM*KCH];   /* 9216 B */

    int o  = threadIdx.x & 127;
    int rg = threadIdx.x >> 7;        /* 0 or 1 */
    int nrep = d_count;
    int nrb  = (nrep + BM - 1) / BM;
    int ntile = nrb * NKC;

    for (int tile = blockIdx.x; tile < ntile; tile += gridDim.x) {
        int kc = tile & (NKC-1);
        int rb = tile >> 2;
        int r0 = rb*BM;
        int cnt = min(BM, nrep - r0);
        int kbase = kc*KCH;

        // stage patch k-slice (scattered gmem -> smem)
        for (int i = threadIdx.x; i < cnt*KCH; i += blockDim.x) {
            int rr = i / KCH;
            int el = i - rr*KCH;
            int e  = kbase + el;
            int t  = d_list[r0 + rr];
            int n  = t >> 14;
            int l  = t & (LL-1);
            int h  = l >> 7;
            int w  = l & 127;
            int c  = e / 9;
            int k9 = e - c*9;
            int di = k9 / 3;
            int dj = k9 - di*3;
            int hr = h + di - 1;
            int wc = w + dj - 1;
            float v = 0.f;
            if (hr >= 0 && hr < HH && wc >= 0 && wc < WW)
                v = fmap[((size_t)(n*CIN + c))*LL + hr*WW + wc];
            patch[rr*KCH + el] = v;
        }
        __syncthreads();

        float acc[8];
        #pragma unroll
        for (int rr = 0; rr < 8; rr++) acc[rr] = 0.f;
        const float* pbase = patch + rg*8*KCH;
        const float* wbase = d_wt4 + (kbase >> 2)*(COUT*4) + o*4;

        #pragma unroll 3
        for (int k0 = 0; k0 < KCH; k0 += 16) {      /* 9 iters, 4 wv in flight */
            float4 wv0 = *reinterpret_cast<const float4*>(wbase + (k0 >> 2)*(COUT*4));
            float4 wv1 = *reinterpret_cast<const float4*>(wbase + ((k0 >> 2) + 1)*(COUT*4));
            float4 wv2 = *reinterpret_cast<const float4*>(wbase + ((k0 >> 2) + 2)*(COUT*4));
            float4 wv3 = *reinterpret_cast<const float4*>(wbase + ((k0 >> 2) + 3)*(COUT*4));
            #pragma unroll
            for (int rr = 0; rr < 8; rr++) {
                const float* pr = pbase + rr*KCH + k0;
                float4 p0 = *reinterpret_cast<const float4*>(pr);
                float4 p1 = *reinterpret_cast<const float4*>(pr + 4);
                float4 p2 = *reinterpret_cast<const float4*>(pr + 8);
                float4 p3 = *reinterpret_cast<const float4*>(pr + 12);
                acc[rr] += wv0.x*p0.x; acc[rr] += wv0.y*p0.y;
                acc[rr] += wv0.z*p0.z; acc[rr] += wv0.w*p0.w;
                acc[rr] += wv1.x*p1.x; acc[rr] += wv1.y*p1.y;
                acc[rr] += wv1.z*p1.z; acc[rr] += wv1.w*p1.w;
                acc[rr] += wv2.x*p2.x; acc[rr] += wv2.y*p2.y;
                acc[rr] += wv2.z*p2.z; acc[rr] += wv2.w*p2.w;
                acc[rr] += wv3.x*p3.x; acc[rr] += wv3.y*p3.y;
                acc[rr] += wv3.z*p3.z; acc[rr] += wv3.w*p3.w;
            }
        }

        #pragma unroll
        for (int rr = 0; rr < 8; rr++) {
            int rid = r0 + rg*8 + rr;
            if (rid < nrep)
                atomicAdd(&d_tmp2[(size_t)rid*COUT + o], acc[rr]);
        }
        __syncthreads();
    }
}

// ---------------- 5. gather (rep lookup + smem transpose + bias) ---------
__global__ void gather_t(const float* __restrict__ bias, float* __restrict__ out) {
    __shared__ float sm[32*129];
    __shared__ int   rids[32];

    int n  = blockIdx.x >> 9;
    int lt = blockIdx.x & 511;
    int l0 = lt << 5;
    int tid = threadIdx.x;

    if (tid < 32) {
        int v = d_summ[(n << 14) + l0 + tid];
        int r = d_table[n*TSIZE + v + TOFF];
        rids[tid] = d_ridx[(n << 14) + r];
    }
    __syncthreads();

    #pragma unroll
    for (int j = 0; j < 4; j++) {
        int idx = tid + j*256;
        int row = idx >> 5;
        int o4  = (idx & 31) << 2;
        float4 v = *reinterpret_cast<const float4*>(
            d_tmp2 + (size_t)rids[row]*COUT + o4);
        float4 b = *reinterpret_cast<const float4*>(bias + o4);
        sm[row*129 + o4 + 0] = v.x + b.x;
        sm[row*129 + o4 + 1] = v.y + b.y;
        sm[row*129 + o4 + 2] = v.z + b.z;
        sm[row*129 + o4 + 3] = v.w + b.w;
    }
    __syncthreads();

    #pragma unroll
    for (int j = 0; j < 4; j++) {
        int idx = tid + j*256;
        int o   = idx >> 3;
        int l4  = (idx & 7) << 2;
        float4 v;
        v.x = sm[(l4 + 0)*129 + o];
        v.y = sm[(l4 + 1)*129 + o];
        v.z = sm[(l4 + 2)*129 + o];
        v.w = sm[(l4 + 3)*129 + o];
        *reinterpret_cast<float4*>(
            out + (((size_t)n*COUT + o) << 14) + l0 + l4) = v;
    }
}

// ---------------- launch ----------------
extern "C" void kernel_launch(void* const* d_in, const int* in_sizes, int n_in,
                              void* d_out, int out_size) {
    const float* fmap   = (const float*)d_in[0];
    const float* weight = (const float*)d_in[1];
    const float* bias   = (const float*)d_in[2];
    float* out = (float*)d_out;

    init_k  <<<(NB*TSIZE + 255)/256, 256>>>();            /* #1 */
    zero_k  <<<(MAXREP*COUT/4 + 255)/256, 256>>>();       /* #2 */
    wt_k    <<<(KK*COUT + 255)/256, 256>>>(weight);       /* #3 */
    summ_k  <<<(NB*HH*(WW/2) + 255)/256, 256>>>(fmap);    /* #4 <- profiled */
    rep_k   <<<(NB*LL + 255)/256, 256>>>();               /* #5 */
    conv4_k <<<592, 256>>>(fmap);                         /* #6 */
    gather_t<<<NB*512, 256>>>(bias, out);                 /* #7 */
}

// round 7
// speedup vs baseline: 1.8386x; 1.5063x over previous
#include <cuda_runtime.h>

#define NB   8
#define CIN  64
#define HH   128
#define WW   128
#define LL   (HH*WW)      /* 16384 */
#define KK   576
#define COUT 128
#define TOFF 4096         /* keys ~N(0,42); 4096 = 98 sigma */
#define TSIZE 8200
#define SENT 0x7FFFFFFF

#define BM     16         /* reps per conv tile */
#define NKC    4          /* split-k chunks */
#define KCH    (KK/NKC)   /* 144 */
#define MAXREP 8192

#define CCH  8            /* summ: channels per smem chunk */
#define SROW 136          /* summ: padded smem row stride (floats) */

// ---------------- scratch (static device globals) ----------------
__device__ int   d_table[NB*TSIZE];
__device__ int   d_summ [NB*LL];
__device__ int   d_ridx [NB*LL];
__device__ int   d_list [NB*LL];
__device__ int   d_count;
__device__ float d_wt4  [KK*COUT];
__device__ float d_tmp2 [(size_t)NB*LL*COUT];

// ---------------- 1a. init table + counter ----------------
__global__ void init_k() {
    int i = blockIdx.x*blockDim.x + threadIdx.x;
    if (i < NB*TSIZE) d_table[i] = SENT;
    if (i == 0) d_count = 0;
}

// ---------------- 1b. zero conv accumulator region ----------------
__global__ void zero_k() {
    int i = blockIdx.x*blockDim.x + threadIdx.x;
    float4 z = {0.f, 0.f, 0.f, 0.f};
    if (i < MAXREP*COUT/4)
        reinterpret_cast<float4*>(d_tmp2)[i] = z;
}

// ---------------- 1c. weight relayout: [k/4][o][4] ----------------
__global__ void wt_k(const float* __restrict__ weight) {
    int i = blockIdx.x*blockDim.x + threadIdx.x;
    if (i >= KK*COUT) return;
    int k = i >> 7;
    int o = i & 127;
    d_wt4[(k >> 2)*(COUT*4) + o*4 + (k & 3)] = weight[o*KK + k];
}

// ---------------- 2. summ (smem-staged): EXACT-order 576-sum -> key -------
// Block = (n, 2 rows). 128 threads, 2 outputs/thread. c in chunks of 8:
// coalesced float4 gmem -> smem (rows h0-1..h0+2, w zero-padded), then the
// dependent add chain reads smem only. Per-accumulator add ORDER is identical
// to the verified reference order (c asc, di asc, then lft,m0,m1 / m0,m1,rgt).
// DO NOT reassociate.
__global__ void __launch_bounds__(128)
summ_k(const float* __restrict__ fmap) {
    __shared__ float sm[CCH*4*SROW];   /* 8c x 4 rows x 136 = 17408 B */

    int bi = blockIdx.x;
    int n  = bi >> 6;
    int h0 = (bi & 63) << 1;
    int tid  = threadIdx.x;
    int w0   = (tid & 63) << 1;
    int hloc = tid >> 6;               /* 0 or 1 */

    float a0 = 0.f, a1 = 0.f;
    const float* base = fmap + (size_t)n*CIN*LL;

    for (int c0 = 0; c0 < CIN; c0 += CCH) {
        __syncthreads();               /* previous chunk consumed */
        /* zero pads (w=-1 and w=128 slots) */
        if (tid < CCH*4) {
            sm[tid*SROW + 3]   = 0.f;
            sm[tid*SROW + 132] = 0.f;
        }
        /* cooperative load: 8c x 4 rows x 32 float4, coalesced */
        #pragma unroll
        for (int j = 0; j < 8; j++) {
            int idx = tid + j*128;     /* 0..1023 */
            int c   = idx >> 7;
            int r   = (idx >> 5) & 3;
            int w4  = idx & 31;
            int hr  = h0 - 1 + r;
            float4 v = {0.f, 0.f, 0.f, 0.f};
            if (hr >= 0 && hr < HH)
                v = *reinterpret_cast<const float4*>(
                    base + (size_t)(c0 + c)*LL + hr*WW + (w4 << 2));
            *reinterpret_cast<float4*>(
                sm + (c*4 + r)*SROW + 4 + (w4 << 2)) = v;
        }
        __syncthreads();

        /* dependent chains read smem only */
        #pragma unroll
        for (int c = 0; c < CCH; c++) {
            #pragma unroll
            for (int di = 0; di < 3; di++) {
                const float* row = sm + (c*4 + hloc + di)*SROW + w0;
                float  lft = row[3];
                float2 m   = *reinterpret_cast<const float2*>(row + 4);
                float  rgt = row[6];
                a0 += lft; a0 += m.x; a0 += m.y;
                a1 += m.x; a1 += m.y; a1 += rgt;
            }
        }
    }

    int h  = h0 + hloc;
    int l0 = h*WW + w0;
    int* sp = d_summ + n*LL + l0;
    int* tb = d_table + n*TSIZE;
    float vals[2] = {a0, a1};
    #pragma unroll
    for (int j = 0; j < 2; j++) {
        float mean = vals[j] / 576.0f;
        float s    = mean * 1000.0f;
        int iv = (int)s;
        iv = max(-TOFF, min(TOFF-1, iv));
        sp[j] = iv;
        atomicMin(&tb[iv + TOFF], l0 + j);
    }
}

// ---------------- 3. compact reps, assign dense rep ids ----------------
__global__ void rep_k() {
    int t = blockIdx.x*blockDim.x + threadIdx.x;
    if (t >= NB*LL) return;
    int n = t >> 14;
    int l = t & (LL-1);
    int v = d_summ[t];
    if (d_table[n*TSIZE + v + TOFF] == l) {
        int idx = atomicAdd(&d_count, 1);
        d_list[idx] = t;
        d_ridx[t]   = idx;
    }
}

// ---------------- 4. conv: split-k x4, BM=16, atomicAdd accumulate -------
__global__ void __launch_bounds__(256)
conv4_k(const float* __restrict__ fmap) {
    __shared__ float patch[BM*KCH];   /* 9216 B */

    int o  = threadIdx.x & 127;
    int rg = threadIdx.x >> 7;
    int nrep = d_count;
    int nrb  = (nrep + BM - 1) / BM;
    int ntile = nrb * NKC;

    for (int tile = blockIdx.x; tile < ntile; tile += gridDim.x) {
        int kc = tile & (NKC-1);
        int rb = tile >> 2;
        int r0 = rb*BM;
        int cnt = min(BM, nrep - r0);
        int kbase = kc*KCH;

        for (int i = threadIdx.x; i < cnt*KCH; i += blockDim.x) {
            int rr = i / KCH;
            int el = i - rr*KCH;
            int e  = kbase + el;
            int t  = d_list[r0 + rr];
            int n  = t >> 14;
            int l  = t & (LL-1);
            int h  = l >> 7;
            int w  = l & 127;
            int c  = e / 9;
            int k9 = e - c*9;
            int di = k9 / 3;
            int dj = k9 - di*3;
            int hr = h + di - 1;
            int wc = w + dj - 1;
            float v = 0.f;
            if (hr >= 0 && hr < HH && wc >= 0 && wc < WW)
                v = fmap[((size_t)(n*CIN + c))*LL + hr*WW + wc];
            patch[rr*KCH + el] = v;
        }
        __syncthreads();

        float acc[8];
        #pragma unroll
        for (int rr = 0; rr < 8; rr++) acc[rr] = 0.f;
        const float* pbase = patch + rg*8*KCH;
        const float* wbase = d_wt4 + (kbase >> 2)*(COUT*4) + o*4;

        #pragma unroll 3
        for (int k0 = 0; k0 < KCH; k0 += 16) {
            float4 wv0 = *reinterpret_cast<const float4*>(wbase + (k0 >> 2)*(COUT*4));
            float4 wv1 = *reinterpret_cast<const float4*>(wbase + ((k0 >> 2) + 1)*(COUT*4));
            float4 wv2 = *reinterpret_cast<const float4*>(wbase + ((k0 >> 2) + 2)*(COUT*4));
            float4 wv3 = *reinterpret_cast<const float4*>(wbase + ((k0 >> 2) + 3)*(COUT*4));
            #pragma unroll
            for (int rr = 0; rr < 8; rr++) {
                const float* pr = pbase + rr*KCH + k0;
                float4 p0 = *reinterpret_cast<const float4*>(pr);
                float4 p1 = *reinterpret_cast<const float4*>(pr + 4);
                float4 p2 = *reinterpret_cast<const float4*>(pr + 8);
                float4 p3 = *reinterpret_cast<const float4*>(pr + 12);
                acc[rr] += wv0.x*p0.x; acc[rr] += wv0.y*p0.y;
                acc[rr] += wv0.z*p0.z; acc[rr] += wv0.w*p0.w;
                acc[rr] += wv1.x*p1.x; acc[rr] += wv1.y*p1.y;
                acc[rr] += wv1.z*p1.z; acc[rr] += wv1.w*p1.w;
                acc[rr] += wv2.x*p2.x; acc[rr] += wv2.y*p2.y;
                acc[rr] += wv2.z*p2.z; acc[rr] += wv2.w*p2.w;
                acc[rr] += wv3.x*p3.x; acc[rr] += wv3.y*p3.y;
                acc[rr] += wv3.z*p3.z; acc[rr] += wv3.w*p3.w;
            }
        }

        #pragma unroll
        for (int rr = 0; rr < 8; rr++) {
            int rid = r0 + rg*8 + rr;
            if (rid < nrep)
                atomicAdd(&d_tmp2[(size_t)rid*COUT + o], acc[rr]);
        }
        __syncthreads();
    }
}

// ---------------- 5. gather (rep lookup + smem transpose + bias) ---------
__global__ void gather_t(const float* __restrict__ bias, float* __restrict__ out) {
    __shared__ float sm[32*129];
    __shared__ int   rids[32];

    int n  = blockIdx.x >> 9;
    int lt = blockIdx.x & 511;
    int l0 = lt << 5;
    int tid = threadIdx.x;

    if (tid < 32) {
        int v = d_summ[(n << 14) + l0 + tid];
        int r = d_table[n*TSIZE + v + TOFF];
        rids[tid] = d_ridx[(n << 14) + r];
    }
    __syncthreads();

    #pragma unroll
    for (int j = 0; j < 4; j++) {
        int idx = tid + j*256;
        int row = idx >> 5;
        int o4  = (idx & 31) << 2;
        float4 v = *reinterpret_cast<const float4*>(
            d_tmp2 + (size_t)rids[row]*COUT + o4);
        float4 b = *reinterpret_cast<const float4*>(bias + o4);
        sm[row*129 + o4 + 0] = v.x + b.x;
        sm[row*129 + o4 + 1] = v.y + b.y;
        sm[row*129 + o4 + 2] = v.z + b.z;
        sm[row*129 + o4 + 3] = v.w + b.w;
    }
    __syncthreads();

    #pragma unroll
    for (int j = 0; j < 4; j++) {
        int idx = tid + j*256;
        int o   = idx >> 3;
        int l4  = (idx & 7) << 2;
        float4 v;
        v.x = sm[(l4 + 0)*129 + o];
        v.y = sm[(l4 + 1)*129 + o];
        v.z = sm[(l4 + 2)*129 + o];
        v.w = sm[(l4 + 3)*129 + o];
        *reinterpret_cast<float4*>(
            out + (((size_t)n*COUT + o) << 14) + l0 + l4) = v;
    }
}

// ---------------- launch ----------------
extern "C" void kernel_launch(void* const* d_in, const int* in_sizes, int n_in,
                              void* d_out, int out_size) {
    const float* fmap   = (const float*)d_in[0];
    const float* weight = (const float*)d_in[1];
    const float* bias   = (const float*)d_in[2];
    float* out = (float*)d_out;

    init_k  <<<(NB*TSIZE + 255)/256, 256>>>();            /* #1 */
    zero_k  <<<(MAXREP*COUT/4 + 255)/256, 256>>>();       /* #2 */
    wt_k    <<<(KK*COUT + 255)/256, 256>>>(weight);       /* #3 */
    summ_k  <<<NB*64, 128>>>(fmap);                       /* #4 <- profiled */
    rep_k   <<<(NB*LL + 255)/256, 256>>>();               /* #5 */
    conv4_k <<<592, 256>>>(fmap);                         /* #6 */
    gather_t<<<NB*512, 256>>>(bias, out);                 /* #7 */
}